// round 11
// baseline (speedup 1.0000x reference)
#include <cuda_runtime.h>
#include <stdint.h>
#include <math.h>

#define B_DIM 4
#define S_DIM 4096
#define D_DIM 1024
#define M_TOK (B_DIM * S_DIM)   // 16384

#define BM 128
#define BN 128
#define BK 32                                // floats; 8 chunks of 16B per row
#define NTHREADS 128
#define A_TILE_FLOATS (128 * 32)             // 4096
#define STAGE_FLOATS (2 * A_TILE_FLOATS)     // 8192 (A then B)
#define STAGE_BYTES (STAGE_FLOATS * 4)       // 32768
#define STAGES 3
#define SMEM_BYTES (STAGES * STAGE_BYTES)    // 98304 (96 KB)

// Scratch (__device__ globals per allocation-free rule)
__device__ float g_X [(size_t)M_TOK * D_DIM];           // 64 MB  (tf32-rounded x)
__device__ float g_W [(size_t)3 * D_DIM * D_DIM];       // 12 MB  (tf32-rounded Wq|Wk|Wv)
__device__ float g_Q [(size_t)M_TOK * D_DIM];           // 64 MB
__device__ float g_K [(size_t)M_TOK * D_DIM];           // 64 MB
__device__ float g_Vt[(size_t)B_DIM * D_DIM * S_DIM];   // 64 MB, [b][d][s]
__device__ float g_S [(size_t)B_DIM * S_DIM * S_DIM];   // 256 MB

__device__ __forceinline__ uint32_t smem_u32(const void* p) {
    uint32_t a;
    asm("{ .reg .u64 t; cvta.to.shared.u64 t, %1; cvt.u32.u64 %0, t; }"
        : "=r"(a) : "l"(p));
    return a;
}

__device__ __forceinline__ float f2tf_f(float f) {
    uint32_t u;
    asm("cvt.rna.tf32.f32 %0, %1;" : "=r"(u) : "f"(f));
    return __uint_as_float(u);
}

__device__ __forceinline__ void cp16(uint32_t dst, const void* src) {
    asm volatile("cp.async.cg.shared.global [%0], [%1], 16;" :: "r"(dst), "l"(src));
}

// ---------------------------------------------------------------------------
// Pre-round fp32 -> tf32-representable fp32 (vectorized, grid-stride)
// ---------------------------------------------------------------------------
__global__ void __launch_bounds__(256) round_tf32_kernel(
    const float4* __restrict__ in, float4* __restrict__ out, int n4)
{
    for (int i = blockIdx.x * 256 + threadIdx.x; i < n4; i += gridDim.x * 256) {
        float4 v = in[i];
        v.x = f2tf_f(v.x); v.y = f2tf_f(v.y);
        v.z = f2tf_f(v.z); v.w = f2tf_f(v.w);
        out[i] = v;
    }
}

// ---------------------------------------------------------------------------
// tf32 mma.sync NT GEMM, 128x128 tile, 128 threads, 2x2 warps of 64x64.
// C[m,n] = sum_k A[m,k]*B[n,k] (+ bias[n]); A,B pre-rounded tf32 fp32.
// proj!=0: grid.z selects W (B = Wbase + z*K*K), bias (b0/b1/b2),
//          output (C0/C1/C2); z==2 does the transposed Vt store + rounding.
// proj==0: batched on grid.z with strides sA/sB/sC; C0/b0 used; mode/rndC args.
// ---------------------------------------------------------------------------
__global__ void __launch_bounds__(NTHREADS, 2) gemm_mma(
    const float* __restrict__ A, const float* __restrict__ Bbase,
    float* __restrict__ C0, float* __restrict__ C1, float* __restrict__ C2,
    const float* __restrict__ b0, const float* __restrict__ b1,
    const float* __restrict__ b2,
    int K, int ldc, size_t sA, size_t sB, size_t sC,
    int proj, int mode, int rndC)
{
    extern __shared__ float sm[];
    const uint32_t smbase = smem_u32(sm);

    const int z = blockIdx.z;
    const float* B;
    float* C;
    const float* bias;
    if (proj) {
        B    = Bbase + (size_t)z * K * K;
        C    = (z == 0) ? C0 : (z == 1) ? C1 : C2;
        bias = (z == 0) ? b0 : (z == 1) ? b1 : b2;
        mode = (z == 2) ? 1 : 0;
        rndC = 1;
    } else {
        A += (size_t)z * sA;
        B  = Bbase + (size_t)z * sB;
        C  = C0 + (size_t)z * sC;
        bias = b0;
    }

    const int tid  = threadIdx.x;
    const int wid  = tid >> 5;
    const int lane = tid & 31;
    const int wm = wid >> 1;          // 0..1  (M warp row, 64 rows each)
    const int wn = wid & 1;           // 0..1  (N warp col, 64 cols each)
    const int r  = lane >> 2;         // 0..7
    const int c  = lane & 3;          // 0..3
    const int m0 = blockIdx.y * BM;
    const int n0 = blockIdx.x * BN;

    // ---- global -> smem mapping: thread t loads full A row t and B row t ----
    const int xr = tid & 7;
    const float* gA = A + (size_t)(m0 + tid) * K;
    const float* gB = B + (size_t)(n0 + tid) * K;
    uint32_t dstA[8], dstB[8];
#pragma unroll
    for (int j = 0; j < 8; j++) {
        dstA[j] = (uint32_t)tid * 128 + (uint32_t)((j ^ xr) << 4);
        dstB[j] = dstA[j] + A_TILE_FLOATS * 4;
    }

    // ---- fragment base offsets (floats within tile) ----
    int aoff[4], boff[8];
#pragma unroll
    for (int mf = 0; mf < 4; mf++) aoff[mf] = (wm * 64 + mf * 16 + r) * 32;
#pragma unroll
    for (int nf = 0; nf < 8; nf++) boff[nf] = (wn * 64 + nf * 8 + r) * 32;

    const int NC = K / BK;

    float acc[4][8][4];
#pragma unroll
    for (int i = 0; i < 4; i++)
#pragma unroll
        for (int j = 0; j < 8; j++)
#pragma unroll
            for (int v = 0; v < 4; v++) acc[i][j][v] = 0.f;

    auto load_chunk = [&](int ch) {
        if (ch < NC) {
            const uint32_t st = smbase + (uint32_t)(ch % STAGES) * STAGE_BYTES;
            const float* pa = gA + ch * BK;
            const float* pb = gB + ch * BK;
#pragma unroll
            for (int j = 0; j < 8; j++) {
                cp16(st + dstA[j], pa + j * 4);
                cp16(st + dstB[j], pb + j * 4);
            }
        }
        asm volatile("cp.async.commit_group;");
    };

    load_chunk(0);
    load_chunk(1);

    for (int i = 0; i < NC; i++) {
        asm volatile("cp.async.wait_group 1;");
        __syncthreads();
        load_chunk(i + 2);

        const uint32_t* As = (const uint32_t*)(sm + (i % STAGES) * STAGE_FLOATS);
        const uint32_t* Bs = As + A_TILE_FLOATS;

#pragma unroll
        for (int s = 0; s < 4; s++) {
            const int koff = (((2 * s) ^ r) << 2) + c;
            const int koff2 = koff ^ 4;
            uint32_t ua[4][4], ub[8][2];
#pragma unroll
            for (int mf = 0; mf < 4; mf++) {
                ua[mf][0] = As[aoff[mf] + koff];
                ua[mf][1] = As[aoff[mf] + 256 + koff];
                ua[mf][2] = As[aoff[mf] + koff2];
                ua[mf][3] = As[aoff[mf] + 256 + koff2];
            }
#pragma unroll
            for (int nf = 0; nf < 8; nf++) {
                ub[nf][0] = Bs[boff[nf] + koff];
                ub[nf][1] = Bs[boff[nf] + koff2];
            }
#pragma unroll
            for (int mf = 0; mf < 4; mf++)
#pragma unroll
                for (int nf = 0; nf < 8; nf++) {
                    asm volatile(
                        "mma.sync.aligned.m16n8k8.row.col.f32.tf32.tf32.f32 "
                        "{%0,%1,%2,%3}, {%4,%5,%6,%7}, {%8,%9}, {%0,%1,%2,%3};"
                        : "+f"(acc[mf][nf][0]), "+f"(acc[mf][nf][1]),
                          "+f"(acc[mf][nf][2]), "+f"(acc[mf][nf][3])
                        : "r"(ua[mf][0]), "r"(ua[mf][1]),
                          "r"(ua[mf][2]), "r"(ua[mf][3]),
                          "r"(ub[nf][0]), "r"(ub[nf][1]));
                }
        }
    }

    if (mode == 0) {
#pragma unroll
        for (int mf = 0; mf < 4; mf++) {
            const int row0 = m0 + wm * 64 + mf * 16 + r;
#pragma unroll
            for (int nf = 0; nf < 8; nf++) {
                const int col = n0 + wn * 64 + nf * 8 + 2 * c;
                float b0v = 0.f, b1v = 0.f;
                if (bias) { b0v = bias[col]; b1v = bias[col + 1]; }
                float2 v0 = { acc[mf][nf][0] + b0v, acc[mf][nf][1] + b1v };
                float2 v1 = { acc[mf][nf][2] + b0v, acc[mf][nf][3] + b1v };
                if (rndC) {
                    v0.x = f2tf_f(v0.x); v0.y = f2tf_f(v0.y);
                    v1.x = f2tf_f(v1.x); v1.y = f2tf_f(v1.y);
                }
                *(float2*)(C + (size_t)row0 * ldc + col) = v0;
                *(float2*)(C + (size_t)(row0 + 8) * ldc + col) = v1;
            }
        }
    } else {
        // transposed epilogue through smem: Ts[n][m], stride 132 (67.6 KB < 96 KB)
        __syncthreads();
        float* Ts = sm;
#pragma unroll
        for (int mf = 0; mf < 4; mf++) {
            const int ml0 = wm * 64 + mf * 16 + r;
#pragma unroll
            for (int nf = 0; nf < 8; nf++) {
                const int nl = wn * 64 + nf * 8 + 2 * c;
                Ts[(nl    ) * 132 + ml0    ] = acc[mf][nf][0];
                Ts[(nl + 1) * 132 + ml0    ] = acc[mf][nf][1];
                Ts[(nl    ) * 132 + ml0 + 8] = acc[mf][nf][2];
                Ts[(nl + 1) * 132 + ml0 + 8] = acc[mf][nf][3];
            }
        }
        __syncthreads();
        const int bbatch = m0 >> 12;
        const int sbase  = m0 & (S_DIM - 1);
#pragma unroll
        for (int it = 0; it < 32; it++) {
            const int idx = tid + it * NTHREADS;   // 0..4095
            const int row = idx >> 5;              // n within tile
            const int f   = (idx & 31) * 4;        // m within tile
            float4 v = *(const float4*)(Ts + row * 132 + f);
            const float bv = bias[n0 + row];
            v.x = f2tf_f(v.x + bv); v.y = f2tf_f(v.y + bv);
            v.z = f2tf_f(v.z + bv); v.w = f2tf_f(v.w + bv);
            *(float4*)(C + ((size_t)bbatch * D_DIM + n0 + row) * S_DIM + sbase + f) = v;
        }
    }
}

// ---------------------------------------------------------------------------
// Row softmax over S_DIM, folded 1/32 scale; writes tf32-rounded probs.
// ---------------------------------------------------------------------------
__global__ void __launch_bounds__(256) softmax_kernel(float* __restrict__ P, float scale)
{
    float4* row = (float4*)(P + (size_t)blockIdx.x * S_DIM);
    const int tid = threadIdx.x;
    __shared__ float sh[32];

    float4 v[4];
    float mx = -INFINITY;
#pragma unroll
    for (int i = 0; i < 4; i++) {
        v[i] = row[tid + i * 256];
        mx = fmaxf(mx, fmaxf(fmaxf(v[i].x, v[i].y), fmaxf(v[i].z, v[i].w)));
    }
#pragma unroll
    for (int o = 16; o; o >>= 1) mx = fmaxf(mx, __shfl_xor_sync(0xffffffffu, mx, o));
    if ((tid & 31) == 0) sh[tid >> 5] = mx;
    __syncthreads();
    if (tid < 32) {
        float t = (tid < 8) ? sh[tid] : -INFINITY;
#pragma unroll
        for (int o = 4; o; o >>= 1) t = fmaxf(t, __shfl_xor_sync(0xffffffffu, t, o));
        if (tid == 0) sh[0] = t;
    }
    __syncthreads();
    mx = sh[0];
    __syncthreads();

    float sum = 0.f;
#pragma unroll
    for (int i = 0; i < 4; i++) {
        v[i].x = __expf((v[i].x - mx) * scale); sum += v[i].x;
        v[i].y = __expf((v[i].y - mx) * scale); sum += v[i].y;
        v[i].z = __expf((v[i].z - mx) * scale); sum += v[i].z;
        v[i].w = __expf((v[i].w - mx) * scale); sum += v[i].w;
    }
#pragma unroll
    for (int o = 16; o; o >>= 1) sum += __shfl_xor_sync(0xffffffffu, sum, o);
    if ((tid & 31) == 0) sh[tid >> 5] = sum;
    __syncthreads();
    if (tid < 32) {
        float t = (tid < 8) ? sh[tid] : 0.f;
#pragma unroll
        for (int o = 4; o; o >>= 1) t += __shfl_xor_sync(0xffffffffu, t, o);
        if (tid == 0) sh[0] = t;
    }
    __syncthreads();
    const float inv = 1.0f / sh[0];

#pragma unroll
    for (int i = 0; i < 4; i++) {
        v[i].x = f2tf_f(v[i].x * inv); v[i].y = f2tf_f(v[i].y * inv);
        v[i].z = f2tf_f(v[i].z * inv); v[i].w = f2tf_f(v[i].w * inv);
        row[tid + i * 256] = v[i];
    }
}

// ---------------------------------------------------------------------------
extern "C" void kernel_launch(void* const* d_in, const int* in_sizes, int n_in,
                              void* d_out, int out_size)
{
    (void)in_sizes; (void)n_in; (void)out_size;
    const float* x  = (const float*)d_in[0];
    const float* Wq = (const float*)d_in[1];
    const float* bq = (const float*)d_in[2];
    const float* Wk = (const float*)d_in[3];
    const float* bk = (const float*)d_in[4];
    const float* Wv = (const float*)d_in[5];
    const float* bv = (const float*)d_in[6];
    float* out = (float*)d_out;

    float *X, *W, *Q, *K, *Vt, *S;
    cudaGetSymbolAddress((void**)&X,  g_X);
    cudaGetSymbolAddress((void**)&W,  g_W);
    cudaGetSymbolAddress((void**)&Q,  g_Q);
    cudaGetSymbolAddress((void**)&K,  g_K);
    cudaGetSymbolAddress((void**)&Vt, g_Vt);
    cudaGetSymbolAddress((void**)&S,  g_S);

    cudaFuncSetAttribute(gemm_mma, cudaFuncAttributeMaxDynamicSharedMemorySize, SMEM_BYTES);

    // Pre-round inputs to tf32-representable fp32
    round_tf32_kernel<<<1024, 256>>>((const float4*)x,  (float4*)X, (M_TOK * D_DIM) / 4);
    round_tf32_kernel<<<256,  256>>>((const float4*)Wq, (float4*)(W + 0 * D_DIM * D_DIM), (D_DIM * D_DIM) / 4);
    round_tf32_kernel<<<256,  256>>>((const float4*)Wk, (float4*)(W + 1 * D_DIM * D_DIM), (D_DIM * D_DIM) / 4);
    round_tf32_kernel<<<256,  256>>>((const float4*)Wv, (float4*)(W + 2 * D_DIM * D_DIM), (D_DIM * D_DIM) / 4);

    const dim3 blk(NTHREADS);

    // Merged QKV projections: grid.z = 0 (Q), 1 (K), 2 (Vt transposed)
    const dim3 gProj(D_DIM / BN, M_TOK / BM, 3);
    gemm_mma<<<gProj, blk, SMEM_BYTES>>>(X, W, Q, K, Vt, bq, bk, bv,
                                         D_DIM, D_DIM, 0, 0, 0, 1, 0, 1);

    // scores = Q . K^T (1/32 folded into softmax); raw fp32 scores
    const dim3 gScore(S_DIM / BN, S_DIM / BM, B_DIM);
    gemm_mma<<<gScore, blk, SMEM_BYTES>>>(Q, K, S, nullptr, nullptr,
                                          nullptr, nullptr, nullptr,
                                          D_DIM, S_DIM,
                                          (size_t)S_DIM * D_DIM,
                                          (size_t)S_DIM * D_DIM,
                                          (size_t)S_DIM * S_DIM, 0, 0, 0);

    softmax_kernel<<<B_DIM * S_DIM, 256>>>(S, 1.0f / 32.0f);

    // out = P . Vt^T (NT: Vt rows are d, ldb = S_DIM); final fp32 output
    const dim3 gPV(D_DIM / BN, S_DIM / BM, B_DIM);
    gemm_mma<<<gPV, blk, SMEM_BYTES>>>(S, Vt, out, nullptr, nullptr,
                                       nullptr, nullptr, nullptr,
                                       S_DIM, D_DIM,
                                       (size_t)S_DIM * S_DIM,
                                       (size_t)D_DIM * S_DIM,
                                       (size_t)S_DIM * D_DIM, 0, 0, 0);
}

// round 12
// speedup vs baseline: 1.4452x; 1.4452x over previous
#include <cuda_runtime.h>
#include <stdint.h>
#include <math.h>

#define B_DIM 4
#define S_DIM 4096
#define D_DIM 1024
#define M_TOK (B_DIM * S_DIM)   // 16384

#define BM 128
#define BN 128
#define BK 32                                // floats; 8 chunks of 16B per row
#define A_TILE_FLOATS (128 * 32)             // 4096
#define STAGE_FLOATS (2 * A_TILE_FLOATS)     // 8192 (A then B)
#define STAGE_BYTES (STAGE_FLOATS * 4)       // 32768
#define STAGES 3
#define SMEM_BYTES (STAGES * STAGE_BYTES)    // 98304

// Scratch (__device__ globals per allocation-free rule)
__device__ float g_X [(size_t)M_TOK * D_DIM];           // 64 MB  (tf32-rounded x)
__device__ float g_W [(size_t)3 * D_DIM * D_DIM];       // 12 MB  (tf32-rounded Wq|Wk|Wv)
__device__ float g_Q [(size_t)M_TOK * D_DIM];           // 64 MB
__device__ float g_K [(size_t)M_TOK * D_DIM];           // 64 MB
__device__ float g_Vt[(size_t)B_DIM * D_DIM * S_DIM];   // 64 MB, [b][d][s]
__device__ float g_S [(size_t)B_DIM * S_DIM * S_DIM];   // 256 MB

__device__ __forceinline__ uint32_t smem_u32(const void* p) {
    uint32_t a;
    asm("{ .reg .u64 t; cvta.to.shared.u64 t, %1; cvt.u32.u64 %0, t; }"
        : "=r"(a) : "l"(p));
    return a;
}

__device__ __forceinline__ float f2tf_f(float f) {
    uint32_t u;
    asm("cvt.rna.tf32.f32 %0, %1;" : "=r"(u) : "f"(f));
    return __uint_as_float(u);
}

__device__ __forceinline__ void cp16(uint32_t dst, const void* src) {
    asm volatile("cp.async.cg.shared.global [%0], [%1], 16;" :: "r"(dst), "l"(src));
}

// ---------------------------------------------------------------------------
// Pre-round fp32 -> tf32-representable fp32 (vectorized, grid-stride)
// ---------------------------------------------------------------------------
__global__ void __launch_bounds__(256) round_tf32_kernel(
    const float4* __restrict__ in, float4* __restrict__ out, int n4)
{
    for (int i = blockIdx.x * 256 + threadIdx.x; i < n4; i += gridDim.x * 256) {
        float4 v = in[i];
        v.x = f2tf_f(v.x); v.y = f2tf_f(v.y);
        v.z = f2tf_f(v.z); v.w = f2tf_f(v.w);
        out[i] = v;
    }
}

// ---------------------------------------------------------------------------
// tf32 mma.sync NT GEMM: 128x128 tile, 256 threads (2x4 warps of 64x32).
// C[m,n] = sum_k A[m,k]*B[n,k] (+ bias[n]); A,B pre-rounded tf32 fp32.
// proj!=0: grid.z selects weights (Bbase + z*K*K), bias (b0/b1/b2), output
//          (C0/C1/C2); z==2 uses the transposed Vt store. rndC forced on.
// proj==0: batched on grid.z with strides sA/sB/sC; uses C0/b0, mode, rndC.
// Smem: 128-byte rows (32 floats), 16B chunk ch stored at ch^(row&7).
// ---------------------------------------------------------------------------
__global__ void __launch_bounds__(256, 2) gemm_mma(
    const float* __restrict__ A, const float* __restrict__ Bbase,
    float* __restrict__ C0, float* __restrict__ C1, float* __restrict__ C2,
    const float* __restrict__ b0, const float* __restrict__ b1,
    const float* __restrict__ b2,
    int K, int ldc, size_t sA, size_t sB, size_t sC,
    int proj, int mode, int rndC)
{
    extern __shared__ float sm[];
    const uint32_t smbase = smem_u32(sm);

    const int z = blockIdx.z;
    const float* B;
    float* C;
    const float* bias;
    if (proj) {
        B    = Bbase + (size_t)z * K * K;
        C    = (z == 0) ? C0 : (z == 1) ? C1 : C2;
        bias = (z == 0) ? b0 : (z == 1) ? b1 : b2;
        mode = (z == 2) ? 1 : 0;
        rndC = 1;
    } else {
        A += (size_t)z * sA;
        B  = Bbase + (size_t)z * sB;
        C  = C0 + (size_t)z * sC;
        bias = b0;
    }

    const int tid  = threadIdx.x;
    const int wid  = tid >> 5;
    const int lane = tid & 31;
    const int wm = wid >> 2;          // 0..1  (M warp row)
    const int wn = wid & 3;           // 0..3  (N warp col)
    const int r  = lane >> 2;         // 0..7
    const int c  = lane & 3;          // 0..3
    const int m0 = blockIdx.y * BM;
    const int n0 = blockIdx.x * BN;

    // ---- global -> smem mapping (swizzled) ----
    const int lrow = tid >> 1;                 // 0..127
    const int o4   = (tid & 1) * 4;            // starting 16B chunk (0 or 4)
    const int xr   = lrow & 7;
    const float* gA = A + (size_t)(m0 + lrow) * K + o4 * 4;
    const float* gB = B + (size_t)(n0 + lrow) * K + o4 * 4;
    uint32_t dstA[4], dstB[4];
#pragma unroll
    for (int j = 0; j < 4; j++) {
        dstA[j] = (uint32_t)lrow * 128 + (uint32_t)(((o4 + j) ^ xr) << 4);
        dstB[j] = dstA[j] + A_TILE_FLOATS * 4;
    }

    // ---- fragment base offsets (floats, within tile) ----
    int aoff[4], boff[4];
#pragma unroll
    for (int mf = 0; mf < 4; mf++) aoff[mf] = (wm * 64 + mf * 16 + r) * 32;
#pragma unroll
    for (int nf = 0; nf < 4; nf++) boff[nf] = (wn * 32 + nf * 8 + r) * 32;

    const int NC = K / BK;

    float acc[4][4][4];
#pragma unroll
    for (int i = 0; i < 4; i++)
#pragma unroll
        for (int j = 0; j < 4; j++)
#pragma unroll
            for (int v = 0; v < 4; v++) acc[i][j][v] = 0.f;

    auto load_chunk = [&](int ch) {
        if (ch < NC) {
            const uint32_t st = smbase + (uint32_t)(ch % STAGES) * STAGE_BYTES;
            const float* pa = gA + ch * BK;
            const float* pb = gB + ch * BK;
#pragma unroll
            for (int j = 0; j < 4; j++) {
                cp16(st + dstA[j], pa + j * 4);
                cp16(st + dstB[j], pb + j * 4);
            }
        }
        asm volatile("cp.async.commit_group;");
    };

    load_chunk(0);
    load_chunk(1);

    for (int i = 0; i < NC; i++) {
        asm volatile("cp.async.wait_group 1;");
        __syncthreads();
        load_chunk(i + 2);

        const uint32_t* As = (const uint32_t*)(sm + (i % STAGES) * STAGE_FLOATS);
        const uint32_t* Bs = As + A_TILE_FLOATS;

#pragma unroll
        for (int s = 0; s < 4; s++) {
            const int koff = (((2 * s) ^ r) << 2) + c;
            const int koff2 = koff ^ 4;
            uint32_t ua[4][4], ub[4][2];
#pragma unroll
            for (int mf = 0; mf < 4; mf++) {
                ua[mf][0] = As[aoff[mf] + koff];
                ua[mf][1] = As[aoff[mf] + 256 + koff];
                ua[mf][2] = As[aoff[mf] + koff2];
                ua[mf][3] = As[aoff[mf] + 256 + koff2];
            }
#pragma unroll
            for (int nf = 0; nf < 4; nf++) {
                ub[nf][0] = Bs[boff[nf] + koff];
                ub[nf][1] = Bs[boff[nf] + koff2];
            }
#pragma unroll
            for (int mf = 0; mf < 4; mf++)
#pragma unroll
                for (int nf = 0; nf < 4; nf++) {
                    asm volatile(
                        "mma.sync.aligned.m16n8k8.row.col.f32.tf32.tf32.f32 "
                        "{%0,%1,%2,%3}, {%4,%5,%6,%7}, {%8,%9}, {%0,%1,%2,%3};"
                        : "+f"(acc[mf][nf][0]), "+f"(acc[mf][nf][1]),
                          "+f"(acc[mf][nf][2]), "+f"(acc[mf][nf][3])
                        : "r"(ua[mf][0]), "r"(ua[mf][1]),
                          "r"(ua[mf][2]), "r"(ua[mf][3]),
                          "r"(ub[nf][0]), "r"(ub[nf][1]));
                }
        }
    }

    if (mode == 0) {
#pragma unroll
        for (int mf = 0; mf < 4; mf++) {
            const int row0 = m0 + wm * 64 + mf * 16 + r;
#pragma unroll
            for (int nf = 0; nf < 4; nf++) {
                const int col = n0 + wn * 32 + nf * 8 + 2 * c;
                float bb0 = 0.f, bb1 = 0.f;
                if (bias) { bb0 = bias[col]; bb1 = bias[col + 1]; }
                float2 v0 = { acc[mf][nf][0] + bb0, acc[mf][nf][1] + bb1 };
                float2 v1 = { acc[mf][nf][2] + bb0, acc[mf][nf][3] + bb1 };
                if (rndC) {
                    v0.x = f2tf_f(v0.x); v0.y = f2tf_f(v0.y);
                    v1.x = f2tf_f(v1.x); v1.y = f2tf_f(v1.y);
                }
                *(float2*)(C + (size_t)row0 * ldc + col) = v0;
                *(float2*)(C + (size_t)(row0 + 8) * ldc + col) = v1;
            }
        }
    } else {
        // transposed epilogue through smem: Ts[n][m], stride 132
        __syncthreads();
        float* Ts = sm;
#pragma unroll
        for (int mf = 0; mf < 4; mf++) {
            const int ml0 = wm * 64 + mf * 16 + r;
#pragma unroll
            for (int nf = 0; nf < 4; nf++) {
                const int nl = wn * 32 + nf * 8 + 2 * c;
                Ts[(nl    ) * 132 + ml0    ] = acc[mf][nf][0];
                Ts[(nl + 1) * 132 + ml0    ] = acc[mf][nf][1];
                Ts[(nl    ) * 132 + ml0 + 8] = acc[mf][nf][2];
                Ts[(nl + 1) * 132 + ml0 + 8] = acc[mf][nf][3];
            }
        }
        __syncthreads();
        const int bbatch = m0 >> 12;
        const int sbase  = m0 & (S_DIM - 1);
#pragma unroll
        for (int it = 0; it < 16; it++) {
            const int idx = tid + it * 256;        // 0..4095
            const int row = idx >> 5;              // n within tile
            const int f   = (idx & 31) * 4;        // m within tile
            float4 v = *(const float4*)(Ts + row * 132 + f);
            const float bv = bias[n0 + row];
            v.x = f2tf_f(v.x + bv); v.y = f2tf_f(v.y + bv);
            v.z = f2tf_f(v.z + bv); v.w = f2tf_f(v.w + bv);
            *(float4*)(C + ((size_t)bbatch * D_DIM + n0 + row) * S_DIM + sbase + f) = v;
        }
    }
}

// ---------------------------------------------------------------------------
// Row softmax over S_DIM, folded 1/32 scale; writes tf32-rounded probs.
// ---------------------------------------------------------------------------
__global__ void __launch_bounds__(256) softmax_kernel(float* __restrict__ P, float scale)
{
    float4* row = (float4*)(P + (size_t)blockIdx.x * S_DIM);
    const int tid = threadIdx.x;
    __shared__ float sh[32];

    float4 v[4];
    float mx = -INFINITY;
#pragma unroll
    for (int i = 0; i < 4; i++) {
        v[i] = row[tid + i * 256];
        mx = fmaxf(mx, fmaxf(fmaxf(v[i].x, v[i].y), fmaxf(v[i].z, v[i].w)));
    }
#pragma unroll
    for (int o = 16; o; o >>= 1) mx = fmaxf(mx, __shfl_xor_sync(0xffffffffu, mx, o));
    if ((tid & 31) == 0) sh[tid >> 5] = mx;
    __syncthreads();
    if (tid < 32) {
        float t = (tid < 8) ? sh[tid] : -INFINITY;
#pragma unroll
        for (int o = 4; o; o >>= 1) t = fmaxf(t, __shfl_xor_sync(0xffffffffu, t, o));
        if (tid == 0) sh[0] = t;
    }
    __syncthreads();
    mx = sh[0];
    __syncthreads();

    float sum = 0.f;
#pragma unroll
    for (int i = 0; i < 4; i++) {
        v[i].x = __expf((v[i].x - mx) * scale); sum += v[i].x;
        v[i].y = __expf((v[i].y - mx) * scale); sum += v[i].y;
        v[i].z = __expf((v[i].z - mx) * scale); sum += v[i].z;
        v[i].w = __expf((v[i].w - mx) * scale); sum += v[i].w;
    }
#pragma unroll
    for (int o = 16; o; o >>= 1) sum += __shfl_xor_sync(0xffffffffu, sum, o);
    if ((tid & 31) == 0) sh[tid >> 5] = sum;
    __syncthreads();
    if (tid < 32) {
        float t = (tid < 8) ? sh[tid] : 0.f;
#pragma unroll
        for (int o = 4; o; o >>= 1) t += __shfl_xor_sync(0xffffffffu, t, o);
        if (tid == 0) sh[0] = t;
    }
    __syncthreads();
    const float inv = 1.0f / sh[0];

#pragma unroll
    for (int i = 0; i < 4; i++) {
        v[i].x = f2tf_f(v[i].x * inv); v[i].y = f2tf_f(v[i].y * inv);
        v[i].z = f2tf_f(v[i].z * inv); v[i].w = f2tf_f(v[i].w * inv);
        row[tid + i * 256] = v[i];
    }
}

// ---------------------------------------------------------------------------
extern "C" void kernel_launch(void* const* d_in, const int* in_sizes, int n_in,
                              void* d_out, int out_size)
{
    (void)in_sizes; (void)n_in; (void)out_size;
    const float* x  = (const float*)d_in[0];
    const float* Wq = (const float*)d_in[1];
    const float* bq = (const float*)d_in[2];
    const float* Wk = (const float*)d_in[3];
    const float* bk = (const float*)d_in[4];
    const float* Wv = (const float*)d_in[5];
    const float* bv = (const float*)d_in[6];
    float* out = (float*)d_out;

    float *X, *W, *Q, *K, *Vt, *S;
    cudaGetSymbolAddress((void**)&X,  g_X);
    cudaGetSymbolAddress((void**)&W,  g_W);
    cudaGetSymbolAddress((void**)&Q,  g_Q);
    cudaGetSymbolAddress((void**)&K,  g_K);
    cudaGetSymbolAddress((void**)&Vt, g_Vt);
    cudaGetSymbolAddress((void**)&S,  g_S);

    cudaFuncSetAttribute(gemm_mma, cudaFuncAttributeMaxDynamicSharedMemorySize, SMEM_BYTES);

    // Pre-round inputs to tf32-representable fp32
    round_tf32_kernel<<<1024, 256>>>((const float4*)x,  (float4*)X, (M_TOK * D_DIM) / 4);
    round_tf32_kernel<<<256,  256>>>((const float4*)Wq, (float4*)(W + 0 * D_DIM * D_DIM), (D_DIM * D_DIM) / 4);
    round_tf32_kernel<<<256,  256>>>((const float4*)Wk, (float4*)(W + 1 * D_DIM * D_DIM), (D_DIM * D_DIM) / 4);
    round_tf32_kernel<<<256,  256>>>((const float4*)Wv, (float4*)(W + 2 * D_DIM * D_DIM), (D_DIM * D_DIM) / 4);

    const dim3 blk(256);

    // Merged QKV projections: grid.z = 0 (Q), 1 (K), 2 (Vt transposed)
    const dim3 gProj(D_DIM / BN, M_TOK / BM, 3);
    gemm_mma<<<gProj, blk, SMEM_BYTES>>>(X, W, Q, K, Vt, bq, bk, bv,
                                         D_DIM, D_DIM, 0, 0, 0, 1, 0, 1);

    // scores = Q . K^T (1/32 folded into softmax); raw fp32 scores
    const dim3 gScore(S_DIM / BN, S_DIM / BM, B_DIM);
    gemm_mma<<<gScore, blk, SMEM_BYTES>>>(Q, K, S, nullptr, nullptr,
                                          nullptr, nullptr, nullptr,
                                          D_DIM, S_DIM,
                                          (size_t)S_DIM * D_DIM,
                                          (size_t)S_DIM * D_DIM,
                                          (size_t)S_DIM * S_DIM, 0, 0, 0);

    softmax_kernel<<<B_DIM * S_DIM, 256>>>(S, 1.0f / 32.0f);

    // out = P . Vt^T (NT: Vt rows are d, ldb = S_DIM); final fp32 output
    const dim3 gPV(D_DIM / BN, S_DIM / BM, B_DIM);
    gemm_mma<<<gPV, blk, SMEM_BYTES>>>(S, Vt, out, nullptr, nullptr,
                                       nullptr, nullptr, nullptr,
                                       S_DIM, D_DIM,
                                       (size_t)S_DIM * S_DIM,
                                       (size_t)D_DIM * S_DIM,
                                       (size_t)S_DIM * D_DIM, 0, 0, 0);
}